// round 7
// baseline (speedup 1.0000x reference)
#include <cuda_runtime.h>
#include <cuda_bf16.h>
#include <cstdint>
#include <cstddef>

// B=4, N=256, E=512. Persistent kernel: 296 CTAs (2/SM) x 256 threads.
// Static job schedule (job = blockIdx.x + wave*GRID), grid barriers between
// phases:
//   P1: G parts(8) = X X^T             (kchunk 64, 192 jobs)
//   P2: S parts(4) = L( L(sum8 G) Kw ) (kchunk 64,  68 jobs)
//   P3: T parts(4) = L( (sum4 S) Qw^T )(kchunk 64,  68 jobs)
//   P4: F parts(4) = (sum4 T) X        (kchunk 64, 160 jobs)
//   P5: out = x*(1 + f - x.f), f = sum4 F parts (512 jobs)
// Part tiles that no job ever writes stay at .bss zeros, so consumer
// part-sums read exact zeros. Deterministic: fixed job->output map,
// disjoint writes, no data-path atomics.

#define BATCH 4
#define NN_   256
#define EE_   512
#define GRID  296
#define PART_G (BATCH * NN_ * NN_)   // 262144 floats
#define PART_F (BATCH * NN_ * EE_)   // 524288 floats

__device__ __align__(16) float g_G[8 * PART_G];
__device__ __align__(16) float g_S[4 * PART_G];
__device__ __align__(16) float g_T[4 * PART_G];
__device__ __align__(16) float g_F[4 * PART_F];

__device__ __align__(128) unsigned bar_cnt[32];   // idx*8 spacing
__device__ __align__(128) unsigned bar_gen[32];

typedef unsigned long long ULL;

__device__ __forceinline__ ULL pack2(float x) {
    ULL r;
    asm("mov.b64 %0, {%1, %1};" : "=l"(r) : "r"(__float_as_uint(x)));
    return r;
}
__device__ __forceinline__ void fma2(ULL& d, ULL a, ULL b) {
    asm("fma.rn.f32x2 %0, %1, %2, %0;" : "+l"(d) : "l"(a), "l"(b));
}
__device__ __forceinline__ float2 unpk(ULL v) {
    unsigned a, b;
    asm("mov.b64 {%0, %1}, %2;" : "=r"(a), "=r"(b) : "l"(v));
    return make_float2(__uint_as_float(a), __uint_as_float(b));
}

__device__ __forceinline__ void grid_barrier(int idx) {
    __syncthreads();
    if (threadIdx.x == 0) {
        volatile unsigned* genp = &bar_gen[idx * 8];
        const unsigned g = *genp;
        __threadfence();
        if (atomicAdd(&bar_cnt[idx * 8], 1u) == GRID - 1) {
            bar_cnt[idx * 8] = 0;
            __threadfence();
            atomicAdd(&bar_gen[idx * 8], 1u);
        } else {
            while (*genp == g) { }
        }
        __threadfence();
    }
    __syncthreads();
}

// One 64(M) x 128(N) x 64(K) job: 4 double-buffered stages of 16 k.
// A row-major (lda), summed over ASUM part buffers (stride PART_G).
// NT: B[j,k] (ldb = row stride), else B[k,j].
// MASK_A: zero A[i,k] for k>i. MASK_C: zero C[i,j] for j>i.
template<bool NT, bool MASK_A, bool MASK_C, int ASUM>
__device__ __forceinline__ void tile_gemm(
    const float* __restrict__ A, const float* __restrict__ B,
    float* __restrict__ C, int lda, int ldb, int ldc,
    int i0, int j0, int kbeg,
    float (*As)[16][68], float (*Bs)[16][132])
{
    const int tid  = threadIdx.x;
    const int ar   = tid >> 2;          // 0..63  A-load row
    const int ac   = (tid & 3) << 2;    // 0,4,8,12
    const int bkr  = tid >> 5;          // 0..7 (+8 it=1)
    const int bjc  = (tid & 31) << 2;   // 0..124
    const int row0 = (tid >> 5) << 3;   // 0..56
    const int col0 = (tid & 31) << 2;   // 0..124

    float4 ra, rb[2];

    auto loadT = [&](int kg) {
        {
            const size_t off = (size_t)(i0 + ar) * lda + (kg + ac);
            float4 v = *(const float4*)&A[off];
            #pragma unroll
            for (int s = 1; s < ASUM; s++) {
                float4 w = *(const float4*)&A[off + (size_t)s * PART_G];
                v.x += w.x; v.y += w.y; v.z += w.z; v.w += w.w;
            }
            if (MASK_A) {
                const int i = i0 + ar, k = kg + ac;
                if (k + 0 > i) v.x = 0.f;
                if (k + 1 > i) v.y = 0.f;
                if (k + 2 > i) v.z = 0.f;
                if (k + 3 > i) v.w = 0.f;
            }
            ra = v;
        }
        #pragma unroll
        for (int it = 0; it < 2; it++) {
            if (NT) {
                const int j = (tid >> 2) + it * 64;
                rb[it] = *(const float4*)&B[(size_t)(j0 + j) * ldb + (kg + ac)];
            } else {
                const int kr = bkr + it * 8;
                rb[it] = *(const float4*)&B[(size_t)(kg + kr) * ldb + (j0 + bjc)];
            }
        }
    };

    auto stageT = [&](int buf) {
        As[buf][ac + 0][ar] = ra.x;
        As[buf][ac + 1][ar] = ra.y;
        As[buf][ac + 2][ar] = ra.z;
        As[buf][ac + 3][ar] = ra.w;
        #pragma unroll
        for (int it = 0; it < 2; it++) {
            if (NT) {
                const int j = (tid >> 2) + it * 64;
                Bs[buf][ac + 0][j] = rb[it].x;
                Bs[buf][ac + 1][j] = rb[it].y;
                Bs[buf][ac + 2][j] = rb[it].z;
                Bs[buf][ac + 3][j] = rb[it].w;
            } else {
                const int kr = bkr + it * 8;
                *(float4*)&Bs[buf][kr][bjc] = rb[it];
            }
        }
    };

    ULL acc[4][4] = {};

    auto compute = [&](int buf) {
        #pragma unroll
        for (int k = 0; k < 16; k++) {
            ulonglong2 aA = *(const ulonglong2*)&As[buf][k][row0];
            ulonglong2 aB = *(const ulonglong2*)&As[buf][k][row0 + 4];
            float4 bv = *(const float4*)&Bs[buf][k][col0];
            const ULL a[4] = {aA.x, aA.y, aB.x, aB.y};
            const ULL b[4] = {pack2(bv.x), pack2(bv.y), pack2(bv.z), pack2(bv.w)};
            #pragma unroll
            for (int u = 0; u < 4; u++)
                #pragma unroll
                for (int v = 0; v < 4; v++)
                    fma2(acc[u][v], a[u], b[v]);
        }
    };

    // 4 stages, double-buffered
    loadT(kbeg);
    stageT(0);
    __syncthreads();
    loadT(kbeg + 16);
    compute(0);
    stageT(1);
    __syncthreads();
    loadT(kbeg + 32);
    compute(1);
    stageT(0);
    __syncthreads();
    loadT(kbeg + 48);
    compute(0);
    stageT(1);
    __syncthreads();
    compute(1);

    #pragma unroll
    for (int u = 0; u < 4; u++) {
        float2 c0 = unpk(acc[u][0]);
        float2 c1 = unpk(acc[u][1]);
        float2 c2 = unpk(acc[u][2]);
        float2 c3 = unpk(acc[u][3]);
        #pragma unroll
        for (int h = 0; h < 2; h++) {
            const int i = i0 + row0 + 2 * u + h;
            float4 o = h ? make_float4(c0.y, c1.y, c2.y, c3.y)
                         : make_float4(c0.x, c1.x, c2.x, c3.x);
            if (MASK_C) {
                const int j = j0 + col0;
                if (j + 0 > i) o.x = 0.f;
                if (j + 1 > i) o.y = 0.f;
                if (j + 2 > i) o.z = 0.f;
                if (j + 3 > i) o.w = 0.f;
            }
            *(float4*)&C[(size_t)i * ldc + (j0 + col0)] = o;
        }
    }
    __syncthreads();   // smem reuse by next job
}

// P1: 6 lower 64x128 tiles of 256x256
__constant__ int t6_r[6] = {0, 1, 2, 2, 3, 3};
__constant__ int t6_c[6] = {0, 0, 0, 1, 0, 1};
// P2/P3: 17 (r, c, kc64) entries per batch, kc <= r
__constant__ int p2_r[17] = {0, 1,1, 2,2,2, 2,2,2, 3,3,3,3, 3,3,3,3};
__constant__ int p2_c[17] = {0, 0,0, 0,0,0, 1,1,1, 0,0,0,0, 1,1,1,1};
__constant__ int p2_k[17] = {0, 0,1, 0,1,2, 0,1,2, 0,1,2,3, 0,1,2,3};
// P4: 10 (r, kc64) entries, kc <= r
__constant__ int p4_r[10] = {0, 1,1, 2,2,2, 3,3,3,3};
__constant__ int p4_k[10] = {0, 0,1, 0,1,2, 0,1,2,3};

__global__ __launch_bounds__(256, 2)
void replicator_fused(const float* __restrict__ X,
                      const float* __restrict__ Qw,
                      const float* __restrict__ Kw,
                      float* __restrict__ out)
{
    __shared__ float As[2][16][68];
    __shared__ float Bs[2][16][132];
    __shared__ float red[8];

    const size_t sX = (size_t)NN_ * EE_;
    const size_t sG = (size_t)NN_ * NN_;
    const int tid = threadIdx.x;

    // ---- P1: 192 jobs: b(4) x tile(6) x kc(8 of 64)
    for (int job = blockIdx.x; job < 192; job += GRID) {
        const int b  = job / 48;
        const int rm = job - b * 48;
        const int t  = rm >> 3;
        const int kc = rm & 7;
        tile_gemm<true, false, false, 1>(
            X + b * sX, X + b * sX, g_G + (size_t)kc * PART_G + b * sG,
            EE_, EE_, NN_, t6_r[t] * 64, t6_c[t] * 128, kc * 64, As, Bs);
    }
    grid_barrier(0);

    // ---- P2: 68 jobs: b(4) x 17, A = sum8 G, masked
    for (int job = blockIdx.x; job < 68; job += GRID) {
        const int b = job / 17;
        const int e = job - b * 17;
        tile_gemm<false, true, true, 8>(
            g_G + b * sG, Kw, g_S + (size_t)p2_k[e] * PART_G + b * sG,
            NN_, NN_, NN_, p2_r[e] * 64, p2_c[e] * 128, p2_k[e] * 64, As, Bs);
    }
    grid_barrier(1);

    // ---- P3: 68 jobs: A = sum4 S (already tril-masked)
    for (int job = blockIdx.x; job < 68; job += GRID) {
        const int b = job / 17;
        const int e = job - b * 17;
        tile_gemm<true, false, true, 4>(
            g_S + b * sG, Qw, g_T + (size_t)p2_k[e] * PART_G + b * sG,
            NN_, NN_, NN_, p2_r[e] * 64, p2_c[e] * 128, p2_k[e] * 64, As, Bs);
    }
    grid_barrier(2);

    // ---- P4: 160 jobs: b(4) x ct(4) x 10, A = sum4 T
    for (int job = blockIdx.x; job < 160; job += GRID) {
        const int b  = job / 40;
        const int rm = job - b * 40;
        const int ct = rm / 10;
        const int e  = rm - ct * 10;
        tile_gemm<false, false, false, 4>(
            g_T + b * sG, X + b * sX, g_F + (size_t)p4_k[e] * PART_F + b * sX,
            NN_, EE_, EE_, p4_r[e] * 64, ct * 128, p4_k[e] * 64, As, Bs);
    }
    grid_barrier(3);

    // ---- P5: 512 jobs, 2 rows each (thread halves)
    const int half = tid >> 7;
    const int tr   = tid & 127;
    for (int job = blockIdx.x; job < 512; job += GRID) {
        const int row = job * 2 + half;           // b*256 + i
        const size_t base = (size_t)row * EE_;

        float4 x = *(const float4*)&X[base + tr * 4];
        float4 f = make_float4(0.f, 0.f, 0.f, 0.f);
        #pragma unroll
        for (int s = 0; s < 4; s++) {
            float4 w = *(const float4*)&g_F[(size_t)s * PART_F + base + tr * 4];
            f.x += w.x; f.y += w.y; f.z += w.z; f.w += w.w;
        }

        float sum = x.x * f.x + x.y * f.y + x.z * f.z + x.w * f.w;
        #pragma unroll
        for (int o = 16; o; o >>= 1)
            sum += __shfl_xor_sync(0xffffffffu, sum, o);

        if ((tid & 31) == 0) red[tid >> 5] = sum;
        __syncthreads();
        const float avg = half ? (red[4] + red[5] + red[6] + red[7])
                               : (red[0] + red[1] + red[2] + red[3]);

        float4 o;
        o.x = x.x * (1.f + f.x - avg);
        o.y = x.y * (1.f + f.y - avg);
        o.z = x.z * (1.f + f.z - avg);
        o.w = x.w * (1.f + f.w - avg);
        *(float4*)&out[base + tr * 4] = o;
        __syncthreads();
    }
}

extern "C" void kernel_launch(void* const* d_in, const int* in_sizes, int n_in,
                              void* d_out, int out_size)
{
    const float* X  = (const float*)d_in[0];   // (4,256,512)
    const float* Qw = (const float*)d_in[1];   // (256,256)
    const float* Kw = (const float*)d_in[2];   // (256,256)
    float* out = (float*)d_out;                // (4,256,512)

    replicator_fused<<<GRID, 256>>>(X, Qw, Kw, out);
}

// round 8
// speedup vs baseline: 1.0114x; 1.0114x over previous
#include <cuda_runtime.h>
#include <cuda_bf16.h>
#include <cstdint>
#include <cstddef>

// B=4, N=256, E=512. Persistent kernel: 296 CTAs (2/SM) x 256 threads.
// Static schedule, grid barriers between phases:
//   P1: G parts(8) = X X^T             (kchunk 64, 192 jobs)
//   P2: S parts(4) = L( L(sum8 G) Kw ) (kchunk 64,  68 jobs)
//   P3: T parts(4) = L( (sum4 S) Qw^T )(kchunk 64,  68 jobs)
//   P4: F parts(4) = (sum4 T) X        (kchunk 64, 160 jobs)
//   P5: out = x*(1 + f - x.f), f = sum4 F parts (512 jobs)
// GEMM compute: mma.sync.m16n8k8 tf32 with 2-way split (hi+lo), fp32 accum:
//   D += Ahi*Bhi + Ahi*Blo + Alo*Bhi   (error ~2^-22, well under 1e-3)
// Part tiles never written stay at .bss zeros. Deterministic.

#define BATCH 4
#define NN_   256
#define EE_   512
#define GRID  296
#define PART_G (BATCH * NN_ * NN_)   // 262144 floats
#define PART_F (BATCH * NN_ * EE_)   // 524288 floats

__device__ __align__(16) float g_G[8 * PART_G];
__device__ __align__(16) float g_S[4 * PART_G];
__device__ __align__(16) float g_T[4 * PART_G];
__device__ __align__(16) float g_F[4 * PART_F];

__device__ __align__(128) unsigned bar_cnt[32];
__device__ __align__(128) unsigned bar_gen[32];

__device__ __forceinline__ void grid_barrier(int idx) {
    __syncthreads();
    if (threadIdx.x == 0) {
        volatile unsigned* genp = &bar_gen[idx * 8];
        const unsigned g = *genp;
        __threadfence();
        if (atomicAdd(&bar_cnt[idx * 8], 1u) == GRID - 1) {
            bar_cnt[idx * 8] = 0;
            __threadfence();
            atomicAdd(&bar_gen[idx * 8], 1u);
        } else {
            while (*genp == g) { }
        }
        __threadfence();
    }
    __syncthreads();
}

__device__ __forceinline__ unsigned f2tf(float x) {
    unsigned r;
    asm("cvt.rna.tf32.f32 %0, %1;" : "=r"(r) : "f"(x));
    return r;
}
__device__ __forceinline__ void mma_tf32(float* c, const unsigned* a,
                                         unsigned b0, unsigned b1) {
    asm("mma.sync.aligned.m16n8k8.row.col.f32.tf32.tf32.f32 "
        "{%0,%1,%2,%3},{%4,%5,%6,%7},{%8,%9},{%0,%1,%2,%3};"
        : "+f"(c[0]), "+f"(c[1]), "+f"(c[2]), "+f"(c[3])
        : "r"(a[0]), "r"(a[1]), "r"(a[2]), "r"(a[3]), "r"(b0), "r"(b1));
}

// One 64(M) x 128(N) x 64(K) job: 4 double-buffered smem stages of k=16.
// Warps: wm = warp&1 (two 32-row halves), wn = warp>>1 (four 32-col quarters).
// Per warp: 2 m16 tiles x 4 n8 tiles, m16n8k8 tf32 split-mma.
// A row-major (lda), summed over ASUM part buffers (stride PART_G).
// NT: B[j,k] (ldb = row stride), else B[k,j].
// MASK_A: zero A[i,k] for k>i. MASK_C: zero C[i,j] for j>i.
template<bool NT, bool MASK_A, bool MASK_C, int ASUM>
__device__ __forceinline__ void tile_gemm(
    const float* __restrict__ A, const float* __restrict__ B,
    float* __restrict__ C, int lda, int ldb, int ldc,
    int i0, int j0, int kbeg,
    float (*As)[16][68], float (*Bs)[16][132])
{
    const int tid  = threadIdx.x;
    const int lane = tid & 31;
    const int warp = tid >> 5;
    const int wm   = warp & 1;
    const int wn   = warp >> 1;

    const int ar   = tid >> 2;          // 0..63  A-load row
    const int ac   = (tid & 3) << 2;    // 0,4,8,12
    const int bkr  = tid >> 5;          // 0..7 (+8 it=1)
    const int bjc  = (tid & 31) << 2;   // 0..124

    float4 ra, rb[2];

    auto loadT = [&](int kg) {
        {
            const size_t off = (size_t)(i0 + ar) * lda + (kg + ac);
            float4 v = *(const float4*)&A[off];
            #pragma unroll
            for (int s = 1; s < ASUM; s++) {
                float4 w = *(const float4*)&A[off + (size_t)s * PART_G];
                v.x += w.x; v.y += w.y; v.z += w.z; v.w += w.w;
            }
            if (MASK_A) {
                const int i = i0 + ar, k = kg + ac;
                if (k + 0 > i) v.x = 0.f;
                if (k + 1 > i) v.y = 0.f;
                if (k + 2 > i) v.z = 0.f;
                if (k + 3 > i) v.w = 0.f;
            }
            ra = v;
        }
        #pragma unroll
        for (int it = 0; it < 2; it++) {
            if (NT) {
                const int j = (tid >> 2) + it * 64;
                rb[it] = *(const float4*)&B[(size_t)(j0 + j) * ldb + (kg + ac)];
            } else {
                const int kr = bkr + it * 8;
                rb[it] = *(const float4*)&B[(size_t)(kg + kr) * ldb + (j0 + bjc)];
            }
        }
    };

    auto stageT = [&](int buf) {
        As[buf][ac + 0][ar] = ra.x;
        As[buf][ac + 1][ar] = ra.y;
        As[buf][ac + 2][ar] = ra.z;
        As[buf][ac + 3][ar] = ra.w;
        #pragma unroll
        for (int it = 0; it < 2; it++) {
            if (NT) {
                const int j = (tid >> 2) + it * 64;
                Bs[buf][ac + 0][j] = rb[it].x;
                Bs[buf][ac + 1][j] = rb[it].y;
                Bs[buf][ac + 2][j] = rb[it].z;
                Bs[buf][ac + 3][j] = rb[it].w;
            } else {
                const int kr = bkr + it * 8;
                *(float4*)&Bs[buf][kr][bjc] = rb[it];
            }
        }
    };

    float acc[2][4][4] = {};   // [m16 tile][n8 tile][c frag]

    const int lr = lane >> 2;   // 0..7
    const int lc = lane & 3;    // 0..3

    auto compute = [&](int buf) {
        #pragma unroll
        for (int kk = 0; kk < 16; kk += 8) {
            // A fragments for 2 m16 tiles, hi/lo split
            unsigned ahi[2][4], alo[2][4];
            #pragma unroll
            for (int t = 0; t < 2; t++) {
                const int r0 = wm * 32 + t * 16 + lr;
                #pragma unroll
                for (int r = 0; r < 4; r++) {
                    const int krow = kk + lc + ((r >> 1) << 2);
                    const int arow = r0 + ((r & 1) << 3);
                    float v = As[buf][krow][arow];
                    unsigned h = f2tf(v);
                    ahi[t][r] = h;
                    alo[t][r] = f2tf(v - __uint_as_float(h));
                }
            }
            // B per n8 tile: 2 frags, hi/lo; then 3 split-mmas per m-tile
            #pragma unroll
            for (int u = 0; u < 4; u++) {
                const int c0 = wn * 32 + u * 8 + lr;
                float v0 = Bs[buf][kk + lc][c0];
                float v1 = Bs[buf][kk + lc + 4][c0];
                unsigned bh0 = f2tf(v0), bh1 = f2tf(v1);
                unsigned bl0 = f2tf(v0 - __uint_as_float(bh0));
                unsigned bl1 = f2tf(v1 - __uint_as_float(bh1));
                #pragma unroll
                for (int t = 0; t < 2; t++) {
                    mma_tf32(acc[t][u], ahi[t], bh0, bh1);
                    mma_tf32(acc[t][u], ahi[t], bl0, bl1);
                    mma_tf32(acc[t][u], alo[t], bh0, bh1);
                }
            }
        }
    };

    // 4 stages, double-buffered
    loadT(kbeg);
    stageT(0);
    __syncthreads();
    loadT(kbeg + 16);
    compute(0);
    stageT(1);
    __syncthreads();
    loadT(kbeg + 32);
    compute(1);
    stageT(0);
    __syncthreads();
    loadT(kbeg + 48);
    compute(0);
    stageT(1);
    __syncthreads();
    compute(1);

    // ---- store: per frag, rows lr (+8), cols 2*lc (+1)
    #pragma unroll
    for (int t = 0; t < 2; t++) {
        #pragma unroll
        for (int u = 0; u < 4; u++) {
            const int jb = j0 + wn * 32 + u * 8 + 2 * lc;
            #pragma unroll
            for (int h = 0; h < 2; h++) {
                const int i = i0 + wm * 32 + t * 16 + lr + h * 8;
                float2 o = make_float2(acc[t][u][2 * h], acc[t][u][2 * h + 1]);
                if (MASK_C) {
                    if (jb + 0 > i) o.x = 0.f;
                    if (jb + 1 > i) o.y = 0.f;
                }
                *(float2*)&C[(size_t)i * ldc + jb] = o;
            }
        }
    }
    __syncthreads();   // smem reuse by next job
}

// P1: 6 lower 64x128 tiles of 256x256
__constant__ int t6_r[6] = {0, 1, 2, 2, 3, 3};
__constant__ int t6_c[6] = {0, 0, 0, 1, 0, 1};
// P2/P3: 17 (r, c, kc64) entries per batch, kc <= r
__constant__ int p2_r[17] = {0, 1,1, 2,2,2, 2,2,2, 3,3,3,3, 3,3,3,3};
__constant__ int p2_c[17] = {0, 0,0, 0,0,0, 1,1,1, 0,0,0,0, 1,1,1,1};
__constant__ int p2_k[17] = {0, 0,1, 0,1,2, 0,1,2, 0,1,2,3, 0,1,2,3};
// P4: 10 (r, kc64) entries, kc <= r
__constant__ int p4_r[10] = {0, 1,1, 2,2,2, 3,3,3,3};
__constant__ int p4_k[10] = {0, 0,1, 0,1,2, 0,1,2,3};

__global__ __launch_bounds__(256, 2)
void replicator_fused(const float* __restrict__ X,
                      const float* __restrict__ Qw,
                      const float* __restrict__ Kw,
                      float* __restrict__ out)
{
    __shared__ float As[2][16][68];
    __shared__ float Bs[2][16][132];
    __shared__ float red[8];

    const size_t sX = (size_t)NN_ * EE_;
    const size_t sG = (size_t)NN_ * NN_;
    const int tid = threadIdx.x;

    // ---- P1: 192 jobs: b(4) x tile(6) x kc(8 of 64)
    for (int job = blockIdx.x; job < 192; job += GRID) {
        const int b  = job / 48;
        const int rm = job - b * 48;
        const int t  = rm >> 3;
        const int kc = rm & 7;
        tile_gemm<true, false, false, 1>(
            X + b * sX, X + b * sX, g_G + (size_t)kc * PART_G + b * sG,
            EE_, EE_, NN_, t6_r[t] * 64, t6_c[t] * 128, kc * 64, As, Bs);
    }
    grid_barrier(0);

    // ---- P2: 68 jobs: b(4) x 17, A = sum8 G, masked
    for (int job = blockIdx.x; job < 68; job += GRID) {
        const int b = job / 17;
        const int e = job - b * 17;
        tile_gemm<false, true, true, 8>(
            g_G + b * sG, Kw, g_S + (size_t)p2_k[e] * PART_G + b * sG,
            NN_, NN_, NN_, p2_r[e] * 64, p2_c[e] * 128, p2_k[e] * 64, As, Bs);
    }
    grid_barrier(1);

    // ---- P3: 68 jobs: A = sum4 S (already tril-masked)
    for (int job = blockIdx.x; job < 68; job += GRID) {
        const int b = job / 17;
        const int e = job - b * 17;
        tile_gemm<true, false, true, 4>(
            g_S + b * sG, Qw, g_T + (size_t)p2_k[e] * PART_G + b * sG,
            NN_, NN_, NN_, p2_r[e] * 64, p2_c[e] * 128, p2_k[e] * 64, As, Bs);
    }
    grid_barrier(2);

    // ---- P4: 160 jobs: b(4) x ct(4) x 10, A = sum4 T
    for (int job = blockIdx.x; job < 160; job += GRID) {
        const int b  = job / 40;
        const int rm = job - b * 40;
        const int ct = rm / 10;
        const int e  = rm - ct * 10;
        tile_gemm<false, false, false, 4>(
            g_T + b * sG, X + b * sX, g_F + (size_t)p4_k[e] * PART_F + b * sX,
            NN_, EE_, EE_, p4_r[e] * 64, ct * 128, p4_k[e] * 64, As, Bs);
    }
    grid_barrier(3);

    // ---- P5: 512 jobs, 2 rows each (thread halves)
    const int half = tid >> 7;
    const int tr   = tid & 127;
    for (int job = blockIdx.x; job < 512; job += GRID) {
        const int row = job * 2 + half;           // b*256 + i
        const size_t base = (size_t)row * EE_;

        float4 x = *(const float4*)&X[base + tr * 4];
        float4 f = make_float4(0.f, 0.f, 0.f, 0.f);
        #pragma unroll
        for (int s = 0; s < 4; s++) {
            float4 w = *(const float4*)&g_F[(size_t)s * PART_F + base + tr * 4];
            f.x += w.x; f.y += w.y; f.z += w.z; f.w += w.w;
        }

        float sum = x.x * f.x + x.y * f.y + x.z * f.z + x.w * f.w;
        #pragma unroll
        for (int o = 16; o; o >>= 1)
            sum += __shfl_xor_sync(0xffffffffu, sum, o);

        if ((tid & 31) == 0) red[tid >> 5] = sum;
        __syncthreads();
        const float avg = half ? (red[4] + red[5] + red[6] + red[7])
                               : (red[0] + red[1] + red[2] + red[3]);

        float4 o;
        o.x = x.x * (1.f + f.x - avg);
        o.y = x.y * (1.f + f.y - avg);
        o.z = x.z * (1.f + f.z - avg);
        o.w = x.w * (1.f + f.w - avg);
        *(float4*)&out[base + tr * 4] = o;
        __syncthreads();
    }
}

extern "C" void kernel_launch(void* const* d_in, const int* in_sizes, int n_in,
                              void* d_out, int out_size)
{
    const float* X  = (const float*)d_in[0];   // (4,256,512)
    const float* Qw = (const float*)d_in[1];   // (256,256)
    const float* Kw = (const float*)d_in[2];   // (256,256)
    float* out = (float*)d_out;                // (4,256,512)

    replicator_fused<<<GRID, 256>>>(X, Qw, Kw, out);
}